// round 2
// baseline (speedup 1.0000x reference)
#include <cuda_runtime.h>
#include <math.h>

// Problem constants
#define B_ 2
#define S_ 2048
#define D_ 1024
#define H_ 16
#define DH_ 64
#define BS_ (B_ * S_)
#define INV_SQRT_DH 0.125f

// Scratch (device globals: no runtime allocation allowed)
__device__ float g_Q[BS_ * D_];      // q projection, [B*S, D] == [B, S, H, DH]
__device__ float g_attn[BS_ * D_];   // per-head attention output (pre out-proj)
__device__ float g_M[H_ * DH_ * DH_]; // folded per-head 64x64 matrices (incl. 1/sqrt(dh))

// ---------------------------------------------------------------------------
// Generic C = A @ W^T + bias (+ residual). A:[M,K] row-major, W:[N,K] row-major.
// 64x64 block tile, BK=16, 256 threads, 4x4 microtile.
// ---------------------------------------------------------------------------
template <bool RESID>
__global__ __launch_bounds__(256) void gemm_xwT(
    const float* __restrict__ A, const float* __restrict__ W,
    const float* __restrict__ bias, const float* __restrict__ R,
    float* __restrict__ C, int M, int N, int K)
{
    __shared__ float As[16][68];  // [k][m], pad 68 keeps f4 aligned + low store conflicts
    __shared__ float Ws[16][68];  // [k][n]
    const int tid = threadIdx.x;
    const int tx = tid & 15, ty = tid >> 4;
    const int m0 = blockIdx.y * 64, n0 = blockIdx.x * 64;

    float acc[4][4] = {};
    for (int k0 = 0; k0 < K; k0 += 16) {
#pragma unroll
        for (int e = 0; e < 4; e++) {
            int idx = tid + e * 256;
            int r = idx >> 4, kk = idx & 15;
            As[kk][r] = A[(size_t)(m0 + r) * K + k0 + kk];
            Ws[kk][r] = W[(size_t)(n0 + r) * K + k0 + kk];
        }
        __syncthreads();
#pragma unroll
        for (int kk = 0; kk < 16; kk++) {
            float4 a4 = *(const float4*)&As[kk][ty * 4];
            float4 b4 = *(const float4*)&Ws[kk][tx * 4];
            float av[4] = {a4.x, a4.y, a4.z, a4.w};
            float bv[4] = {b4.x, b4.y, b4.z, b4.w};
#pragma unroll
            for (int i = 0; i < 4; i++)
#pragma unroll
                for (int j = 0; j < 4; j++) acc[i][j] += av[i] * bv[j];
        }
        __syncthreads();
    }
#pragma unroll
    for (int i = 0; i < 4; i++) {
        int m = m0 + ty * 4 + i;
#pragma unroll
        for (int j = 0; j < 4; j++) {
            int n = n0 + tx * 4 + j;
            float v = acc[i][j] + bias[n];
            if (RESID) v += R[(size_t)m * N + n];
            C[(size_t)m * N + n] = v;
        }
    }
}

// ---------------------------------------------------------------------------
// Precompute M_h[d][f] = sum_e W_q[e, h*DH+d] * W_v[e, h*DH+f], scaled by 1/sqrt(dh).
// One block per head. 256 threads, 4x4 microtile over the 64x64 output.
// ---------------------------------------------------------------------------
__global__ __launch_bounds__(256) void compute_M_kernel(
    const float* __restrict__ Wq, const float* __restrict__ Wv)
{
    __shared__ float Aq[32][68];
    __shared__ float Av[32][68];
    const int h = blockIdx.x;
    const int tid = threadIdx.x;
    const int tx = tid & 15, ty = tid >> 4;

    float acc[4][4] = {};
    for (int e0 = 0; e0 < D_; e0 += 32) {
#pragma unroll
        for (int e = 0; e < 8; e++) {
            int idx = tid + e * 256;
            int ee = idx >> 6, c = idx & 63;
            Aq[ee][c] = Wq[(size_t)(e0 + ee) * D_ + h * DH_ + c];
            Av[ee][c] = Wv[(size_t)(e0 + ee) * D_ + h * DH_ + c];
        }
        __syncthreads();
#pragma unroll
        for (int ee = 0; ee < 32; ee++) {
            float4 a4 = *(const float4*)&Aq[ee][ty * 4];
            float4 b4 = *(const float4*)&Av[ee][tx * 4];
            float av[4] = {a4.x, a4.y, a4.z, a4.w};
            float bv[4] = {b4.x, b4.y, b4.z, b4.w};
#pragma unroll
            for (int i = 0; i < 4; i++)
#pragma unroll
                for (int j = 0; j < 4; j++) acc[i][j] += av[i] * bv[j];
        }
        __syncthreads();
    }
#pragma unroll
    for (int i = 0; i < 4; i++)
#pragma unroll
        for (int j = 0; j < 4; j++)
            g_M[h * DH_ * DH_ + (ty * 4 + i) * DH_ + tx * 4 + j] =
                acc[i][j] * INV_SQRT_DH;
}

// ---------------------------------------------------------------------------
// Flash-style L2 attention. One block = one (b,h) + a 64-query tile.
// Scores = 2/sqrt(dh) * q_s.q_t - ||q_t||^2/sqrt(dh)  (row constant cancelled),
// online softmax over key tiles, O = P @ Q(keys), epilogue O2 = (O/l) @ M_h.
// All smem rows padded to 65 floats: scalar accesses land at <=2-way conflicts.
// ---------------------------------------------------------------------------
__global__ __launch_bounds__(256) void attn_kernel(const int* __restrict__ mask)
{
    extern __shared__ float sm[];
    float* Qs = sm;               // [64][65] query tile [r][d]
    float* Ks = sm + 64 * 65;     // [64][65] key tile [t][d] (also V; also M_h at epilogue)
    float* Ps = sm + 2 * 64 * 65; // [64][65] P tile [r][t] (also normalized O at epilogue)
    float* kb = sm + 3 * 64 * 65; // [64] per-key bias (masked)

    const int tid = threadIdx.x;
    const int tx = tid & 15, ty = tid >> 4;
    const int qt = blockIdx.x;
    const int b = blockIdx.y >> 4;   // / H_
    const int h = blockIdx.y & 15;   // % H_
    const float* Qg = g_Q + (size_t)(b * S_) * D_ + h * DH_;

    // Load Q tile (64 rows x 64 d), float4 global reads, scalar smem stores.
#pragma unroll
    for (int e = 0; e < 4; e++) {
        int idx = tid + e * 256;
        int r = idx >> 4, c4 = idx & 15;
        float4 v = *(const float4*)&Qg[(size_t)(qt * 64 + r) * D_ + c4 * 4];
        Qs[r * 65 + c4 * 4 + 0] = v.x;
        Qs[r * 65 + c4 * 4 + 1] = v.y;
        Qs[r * 65 + c4 * 4 + 2] = v.z;
        Qs[r * 65 + c4 * 4 + 3] = v.w;
    }

    float Oacc[4][4] = {};
    float mrow[4], lrow[4];
#pragma unroll
    for (int i = 0; i < 4; i++) { mrow[i] = -1e30f; lrow[i] = 0.0f; }

    for (int kt = 0; kt < S_ / 64; kt++) {
        __syncthreads();  // prev PV done (and Q tile visible on iter 0)
        // Load key tile
#pragma unroll
        for (int e = 0; e < 4; e++) {
            int idx = tid + e * 256;
            int r = idx >> 4, c4 = idx & 15;
            float4 v = *(const float4*)&Qg[(size_t)(kt * 64 + r) * D_ + c4 * 4];
            Ks[r * 65 + c4 * 4 + 0] = v.x;
            Ks[r * 65 + c4 * 4 + 1] = v.y;
            Ks[r * 65 + c4 * 4 + 2] = v.z;
            Ks[r * 65 + c4 * 4 + 3] = v.w;
        }
        __syncthreads();
        // Per-key bias: -||q_t||^2/sqrt(dh), or -9e15 if masked
        if (tid < 64) {
            float s = 0.0f;
#pragma unroll
            for (int d = 0; d < 64; d++) { float q = Ks[tid * 65 + d]; s += q * q; }
            int mv = mask[b * S_ + kt * 64 + tid];
            kb[tid] = (mv == 0) ? -9e15f : (-s * INV_SQRT_DH);
        }
        __syncthreads();

        // S tile = Q @ K^T (4x4 microtile per thread)
        float sc[4][4] = {};
#pragma unroll
        for (int d = 0; d < 64; d++) {
            float av[4], bv[4];
#pragma unroll
            for (int i = 0; i < 4; i++) av[i] = Qs[(ty * 4 + i) * 65 + d];
#pragma unroll
            for (int j = 0; j < 4; j++) bv[j] = Ks[(tx * 4 + j) * 65 + d];
#pragma unroll
            for (int i = 0; i < 4; i++)
#pragma unroll
                for (int j = 0; j < 4; j++) sc[i][j] += av[i] * bv[j];
        }
        const float twoinv = 2.0f * INV_SQRT_DH;
#pragma unroll
        for (int i = 0; i < 4; i++)
#pragma unroll
            for (int j = 0; j < 4; j++)
                sc[i][j] = sc[i][j] * twoinv + kb[tx * 4 + j];

        // Online softmax (rows live in 16-lane groups along tx)
#pragma unroll
        for (int i = 0; i < 4; i++) {
            float mloc = fmaxf(fmaxf(sc[i][0], sc[i][1]), fmaxf(sc[i][2], sc[i][3]));
#pragma unroll
            for (int off = 8; off > 0; off >>= 1)
                mloc = fmaxf(mloc, __shfl_xor_sync(0xffffffffu, mloc, off, 16));
            float mnew = fmaxf(mrow[i], mloc);
            float alpha = __expf(mrow[i] - mnew);
            float psum = 0.0f;
#pragma unroll
            for (int j = 0; j < 4; j++) {
                float p = __expf(sc[i][j] - mnew);
                sc[i][j] = p;
                psum += p;
            }
#pragma unroll
            for (int off = 8; off > 0; off >>= 1)
                psum += __shfl_xor_sync(0xffffffffu, psum, off, 16);
            lrow[i] = lrow[i] * alpha + psum;
            mrow[i] = mnew;
#pragma unroll
            for (int j = 0; j < 4; j++) Oacc[i][j] *= alpha;
#pragma unroll
            for (int j = 0; j < 4; j++)
                Ps[(ty * 4 + i) * 65 + tx * 4 + j] = sc[i][j];
        }
        __syncthreads();

        // O += P @ K (values are the keys themselves)
#pragma unroll
        for (int t = 0; t < 64; t++) {
            float av[4], bv[4];
#pragma unroll
            for (int i = 0; i < 4; i++) av[i] = Ps[(ty * 4 + i) * 65 + t];
#pragma unroll
            for (int j = 0; j < 4; j++) bv[j] = Ks[t * 65 + tx * 4 + j];
#pragma unroll
            for (int i = 0; i < 4; i++)
#pragma unroll
                for (int j = 0; j < 4; j++) Oacc[i][j] += av[i] * bv[j];
        }
    }

    // Epilogue: normalize, then O2 = (O/l) @ M_h  (M already includes 1/sqrt(dh))
    __syncthreads();
#pragma unroll
    for (int i = 0; i < 4; i++) {
        float inv = 1.0f / lrow[i];
#pragma unroll
        for (int j = 0; j < 4; j++)
            Ps[(ty * 4 + i) * 65 + tx * 4 + j] = Oacc[i][j] * inv;
    }
#pragma unroll
    for (int e = 0; e < 16; e++) {
        int idx = tid + e * 256;
        int d = idx >> 6, f = idx & 63;
        Ks[d * 65 + f] = g_M[h * DH_ * DH_ + idx];
    }
    __syncthreads();

    float o2[4][4] = {};
#pragma unroll
    for (int d = 0; d < 64; d++) {
        float av[4], bv[4];
#pragma unroll
        for (int i = 0; i < 4; i++) av[i] = Ps[(ty * 4 + i) * 65 + d];
#pragma unroll
        for (int j = 0; j < 4; j++) bv[j] = Ks[d * 65 + tx * 4 + j];
#pragma unroll
        for (int i = 0; i < 4; i++)
#pragma unroll
            for (int j = 0; j < 4; j++) o2[i][j] += av[i] * bv[j];
    }
    float* Og = g_attn + (size_t)(b * S_) * D_ + h * DH_;
#pragma unroll
    for (int i = 0; i < 4; i++)
#pragma unroll
        for (int j = 0; j < 4; j++)
            Og[(size_t)(qt * 64 + ty * 4 + i) * D_ + tx * 4 + j] = o2[i][j];
}

// ---------------------------------------------------------------------------
// Launch: Q-proj GEMM -> M precompute -> attention -> out GEMM (+x residual)
// ---------------------------------------------------------------------------
extern "C" void kernel_launch(void* const* d_in, const int* in_sizes, int n_in,
                              void* d_out, int out_size)
{
    // metadata order: x, W_q, b_q, W_v, W_out, b_out, mask
    const float* x     = (const float*)d_in[0];
    const float* W_q   = (const float*)d_in[1];
    const float* b_q   = (const float*)d_in[2];
    const float* W_v   = (const float*)d_in[3];
    const float* W_out = (const float*)d_in[4];
    const float* b_out = (const float*)d_in[5];
    const int*   mask  = (const int*)d_in[6];
    float* out = (float*)d_out;

    float *pQ, *pA;
    cudaGetSymbolAddress((void**)&pQ, g_Q);
    cudaGetSymbolAddress((void**)&pA, g_attn);

    dim3 gge(D_ / 64, BS_ / 64);

    // 1) Q = x @ W_q^T + b_q
    gemm_xwT<false><<<gge, 256>>>(x, W_q, b_q, nullptr, pQ, BS_, D_, D_);

    // 2) per-head folded matrices M_h
    compute_M_kernel<<<H_, 256>>>(W_q, W_v);

    // 3) attention (flash-style) + per-head epilogue
    const int smemB = (3 * 64 * 65 + 64) * (int)sizeof(float);  // 50176 B
    cudaFuncSetAttribute(attn_kernel, cudaFuncAttributeMaxDynamicSharedMemorySize, smemB);
    attn_kernel<<<dim3(S_ / 64, B_ * H_), 256, smemB>>>(mask);

    // 4) out = x + attn @ W_out^T + b_out
    gemm_xwT<true><<<gge, 256>>>(pA, W_out, b_out, x, out, BS_, D_, D_);
}